// round 14
// baseline (speedup 1.0000x reference)
#include <cuda_runtime.h>
#include <cuda_bf16.h>
#include <cstdint>

#define BB 64
#define SSL 512
#define II 1024
#define HH 1024
#define RING (256*1024)

typedef unsigned int u32;
typedef unsigned long long u64;

// ---------------- persistent device scratch ----------------
__device__ __align__(256) __nv_bfloat16 g_Ahi[(size_t)BB*SSL*II];
__device__ __align__(256) __nv_bfloat16 g_Alo[(size_t)BB*SSL*II];
__device__ __align__(256) __nv_bfloat16 g_Wihh[II*HH];
__device__ __align__(256) __nv_bfloat16 g_Wihl[II*HH];
__device__ __align__(256) __nv_bfloat16 g_Whhh[HH*HH];
__device__ __align__(256) __nv_bfloat16 g_Whhl[HH*HH];
__device__ __align__(256) __nv_bfloat16 g_rh[2*RING];
__device__ __align__(256) __nv_bfloat16 g_rl[2*RING];
__device__ u32 g_flags[128];

// ---------------- helpers ----------------
__device__ __forceinline__ u32 smem_u32(const void* p) {
    u32 a; asm("{ .reg .u64 t; cvta.to.shared.u64 t, %1; cvt.u32.u64 %0, t; }" : "=r"(a) : "l"(p));
    return a;
}
__device__ __forceinline__ u32 pack_bf16x2(float a, float b) {
    u32 r; asm("cvt.rn.bf16x2.f32 %0, %1, %2;" : "=r"(r) : "f"(b), "f"(a));
    return r;
}
__device__ __forceinline__ float bf16_hi_f32(float x) {
    u32 r; asm("cvt.rn.bf16x2.f32 %0, %1, %2;" : "=r"(r) : "f"(0.0f), "f"(x));
    return __uint_as_float(r << 16);
}
__device__ __forceinline__ float fast_tanh(float x) {
    float a = fabsf(x);
    float e = __expf(-2.0f * a);
    float r = __fdividef(1.0f - e, 1.0f + e);
    return copysignf(r, x);
}
#define CP16(smem_addr, gptr) \
    asm volatile("cp.async.cg.shared.global [%0], [%1], 16;" :: "r"(smem_addr), "l"(gptr))
#define CP_COMMIT() asm volatile("cp.async.commit_group;" ::: "memory")
#define CP_WAIT(n)  asm volatile("cp.async.wait_group %0;" :: "n"(n) : "memory")

__device__ __forceinline__ void ldmx4(u32* r, u32 addr) {
    asm volatile("ldmatrix.sync.aligned.m8n8.x4.shared.b16 {%0,%1,%2,%3}, [%4];"
        : "=r"(r[0]), "=r"(r[1]), "=r"(r[2]), "=r"(r[3]) : "r"(addr));
}
__device__ __forceinline__ void mma16816(float* c, const u32* a, const u32* b) {
    asm volatile("mma.sync.aligned.m16n8k16.row.col.f32.bf16.bf16.f32 "
        "{%0,%1,%2,%3}, {%4,%5,%6,%7}, {%8,%9}, {%0,%1,%2,%3};"
        : "+f"(c[0]), "+f"(c[1]), "+f"(c[2]), "+f"(c[3])
        : "r"(a[0]), "r"(a[1]), "r"(a[2]), "r"(a[3]), "r"(b[0]), "r"(b[1]));
}

// ============================================================================
// fp32 -> bf16 hi/lo split. which: 0=inputs, 1=Wih, 2=Whh, 3=h0->ring slot0
// ============================================================================
__global__ void split_kernel(const float* __restrict__ src, int which, int n4)
{
    int i = blockIdx.x * blockDim.x + threadIdx.x;
    if (i >= n4) return;
    __nv_bfloat16 *hi, *lo;
    if      (which == 0) { hi = g_Ahi;  lo = g_Alo;  }
    else if (which == 1) { hi = g_Wihh; lo = g_Wihl; }
    else if (which == 2) { hi = g_Whhh; lo = g_Whhl; }
    else                 { hi = g_rh;   lo = g_rl;   }
    float4 v = ((const float4*)src)[i];
    float h0 = bf16_hi_f32(v.x), h1 = bf16_hi_f32(v.y);
    float h2 = bf16_hi_f32(v.z), h3 = bf16_hi_f32(v.w);
    ((u32*)hi)[2*i+0] = pack_bf16x2(v.x, v.y);
    ((u32*)hi)[2*i+1] = pack_bf16x2(v.z, v.w);
    ((u32*)lo)[2*i+0] = pack_bf16x2(v.x - h0, v.y - h1);
    ((u32*)lo)[2*i+1] = pack_bf16x2(v.z - h2, v.w - h3);
}

// ============================================================================
// Phase 1: pre = inputs @ Wih^T + bih + bhh   (mma.sync bf16, 3-product split)
// 128x128 tile, KC=64, cp.async double buffer, 256 thr, warp tile 64x32.
// ============================================================================
#define P1_AST 72
#define P1_TILE (128*P1_AST*2)     // 18432 B
#define P1_BUF  (4*P1_TILE)        // Ah Al Bh Bl
#define P1_BYTES (2*P1_BUF)        // 147456 B

__global__ __launch_bounds__(256, 1)
void gemm1_kernel(const float* __restrict__ bih, const float* __restrict__ bhh,
                  float* __restrict__ out)
{
    extern __shared__ char smem[];
    const u32 sb = smem_u32(smem);
    const int tid = threadIdx.x, wid = tid >> 5, lane = tid & 31;
    const int bm = blockIdx.y * 128, bn = blockIdx.x * 128;
    const int m_base = (wid >> 2) * 64;     // 0 or 64
    const int n_base = (wid & 3) * 32;      // 0,32,64,96

    auto load_chunk = [&](int s, int buf) {
        const int k0 = s * 64;
        const u32 base = sb + buf * P1_BUF;
#pragma unroll
        for (int it = 0; it < 4; it++) {
            int v = tid + it * 256;        // 0..1023
            int r = v >> 3, c = (v & 7) * 8;
            u32 so = (u32)(r * P1_AST + c) * 2;
            size_t gA = (size_t)(bm + r) * II + k0 + c;
            size_t gW = (size_t)(bn + r) * II + k0 + c;
            CP16(base + so,               g_Ahi + gA);
            CP16(base + P1_TILE + so,     g_Alo + gA);
            CP16(base + 2*P1_TILE + so,   g_Wihh + gW);
            CP16(base + 3*P1_TILE + so,   g_Wihl + gW);
        }
    };

    float acc[4][4][4];
#pragma unroll
    for (int i = 0; i < 4; i++)
#pragma unroll
        for (int j = 0; j < 4; j++)
#pragma unroll
            for (int q = 0; q < 4; q++) acc[i][j][q] = 0.0f;

    load_chunk(0, 0); CP_COMMIT();
    for (int s = 0; s < 16; s++) {
        const int b = s & 1;
        if (s + 1 < 16) load_chunk(s + 1, b ^ 1);
        CP_COMMIT();
        CP_WAIT(1);
        __syncthreads();
        const u32 abase = sb + b * P1_BUF;
        const u32 bbase = abase + 2 * P1_TILE;
#pragma unroll
        for (int ks = 0; ks < 4; ks++) {
            const int k16 = ks * 16;
            const u32 acol = (u32)(k16 + ((lane >> 4) << 3));
            const u32 arow = (u32)(m_base + (lane & 15));
            const u32 brow = (u32)(n_base + (lane & 7) + ((lane & 16) >> 1));
            const u32 bcol = (u32)(k16 + (lane & 8));
            u32 af[4][4], bh[8], bl[8];
#pragma unroll
            for (int j = 0; j < 2; j++) {
                u32 bd = bbase + ((brow + j*16) * P1_AST + bcol) * 2;
                ldmx4(&bh[j*4], bd);
                ldmx4(&bl[j*4], bd + P1_TILE);
            }
#pragma unroll
            for (int im = 0; im < 4; im++)
                ldmx4(af[im], abase + ((arow + im*16) * P1_AST + acol) * 2);   // Ah
#pragma unroll
            for (int im = 0; im < 4; im++)
#pragma unroll
                for (int jn = 0; jn < 4; jn++) {
                    mma16816(acc[im][jn], af[im], &bh[jn*2]);   // Ah*Bh
                    mma16816(acc[im][jn], af[im], &bl[jn*2]);   // Ah*Bl
                }
#pragma unroll
            for (int im = 0; im < 4; im++)
                ldmx4(af[im], abase + P1_TILE + ((arow + im*16) * P1_AST + acol) * 2);  // Al
#pragma unroll
            for (int im = 0; im < 4; im++)
#pragma unroll
                for (int jn = 0; jn < 4; jn++)
                    mma16816(acc[im][jn], af[im], &bh[jn*2]);   // Al*Bh
        }
        __syncthreads();
    }

    // epilogue: add biases, store fp32
#pragma unroll
    for (int im = 0; im < 4; im++) {
        int r0 = bm + m_base + im*16 + (lane >> 2);
#pragma unroll
        for (int jn = 0; jn < 4; jn++) {
            int n = bn + n_base + jn*8 + (lane & 3) * 2;
            float2 b1 = *(const float2*)(bih + n);
            float2 b2 = *(const float2*)(bhh + n);
            float bx = b1.x + b2.x, by = b1.y + b2.y;
            float2 v0 = make_float2(acc[im][jn][0] + bx, acc[im][jn][1] + by);
            float2 v1 = make_float2(acc[im][jn][2] + bx, acc[im][jn][3] + by);
            *(float2*)(out + (size_t)r0 * HH + n)       = v0;
            *(float2*)(out + (size_t)(r0+8) * HH + n)   = v1;
        }
    }
}

// ============================================================================
// Phase 2 v2: 128 blocks = 8 mt (32 rows) x 16 nt (64 cols), 256 thr (8 warps,
// warp tile 16x16). Whh-hi (64 n-rows x 1024 k) persistent in SMEM; Whh-lo
// streamed per group (disjoint per block -> only 2MB/group chip-wide). A
// (hidden ring) redundancy cut 32x -> 16x. Flag-array grid barrier (parallel
// stores/polls, epoch-based for graph replay).
// ============================================================================
#define Q_BH_STRIDE 1032
#define Q_BH_BYTES (64*Q_BH_STRIDE*2)     // 132096
#define Q_CH_STRIDE 136
#define Q_BL_CHUNK (64*Q_CH_STRIDE*2)     // 17408
#define Q_A_CHUNK  (32*Q_CH_STRIDE*2)     // 8704 (per hi|lo)
#define Q_BYTES (Q_BH_BYTES + 2*Q_BL_CHUNK + 4*Q_A_CHUNK)   // 201728

__global__ __launch_bounds__(256, 1)
void rnn2_kernel(float* __restrict__ out)
{
    extern __shared__ char smem[];
    const u32 sb   = smem_u32(smem);
    const u32 sbBh = sb;
    const u32 sbBl = sb + Q_BH_BYTES;
    const u32 sbA  = sbBl + 2*Q_BL_CHUNK;
    const int tid = threadIdx.x, wid = tid >> 5, lane = tid & 31;
    const int bid = blockIdx.x;
    const int mt  = bid >> 4;          // 0..7  -> rows mt*32
    const int ntc = bid & 15;          // 0..15 -> cols ntc*64
    const int wm = wid >> 2, wn = wid & 3;   // warp tile 16m x 16n

    const u32 my_base = *((volatile u32*)&g_flags[bid]);   // replay epoch

    // ---- persistent Whh-hi slice: 64 n-rows x 1024 k ----
#pragma unroll
    for (int it = 0; it < 32; it++) {
        int v = tid + it * 256;            // 0..8191
        int r = v >> 7, c = (v & 127) * 8;
        CP16(sbBh + (u32)(r * Q_BH_STRIDE + c) * 2,
             g_Whhh + (size_t)(ntc*64 + r) * HH + c);
    }
    CP_COMMIT(); CP_WAIT(0);
    __syncthreads();

    for (int g = 0; g < 128; g++) {
        const int rslot = g & 1, wslot = rslot ^ 1;
        const __nv_bfloat16* Ah = g_rh + (size_t)rslot * RING;
        const __nv_bfloat16* Al = g_rl + (size_t)rslot * RING;

        auto load_chunk = [&](int s, int buf) {
            const int k0 = s * 128;
            const u32 blb = sbBl + buf * Q_BL_CHUNK;
            const u32 aab = sbA + buf * (2 * Q_A_CHUNK);
#pragma unroll
            for (int it = 0; it < 4; it++) {           // Bl: 64 x 128
                int v = tid + it * 256;                // 0..1023
                int r = v >> 4, c = (v & 15) * 8;
                CP16(blb + (u32)(r * Q_CH_STRIDE + c) * 2,
                     g_Whhl + (size_t)(ntc*64 + r) * HH + k0 + c);
            }
#pragma unroll
            for (int it = 0; it < 2; it++) {           // A hi+lo: 32 x 128
                int v = tid + it * 256;                // 0..511
                int r = v >> 4, c = (v & 15) * 8;
                u32 so = (u32)(r * Q_CH_STRIDE + c) * 2;
                size_t ga = (size_t)(mt*32 + r) * HH + k0 + c;
                CP16(aab + so,             Ah + ga);
                CP16(aab + Q_A_CHUNK + so, Al + ga);
            }
        };

        float acc[3][2][4];
#pragma unroll
        for (int p = 0; p < 3; p++)
#pragma unroll
            for (int j = 0; j < 2; j++)
#pragma unroll
                for (int q = 0; q < 4; q++) acc[p][j][q] = 0.0f;

        load_chunk(0, 0); CP_COMMIT();
        for (int s = 0; s < 8; s++) {
            const int b = s & 1;
            if (s + 1 < 8) load_chunk(s + 1, b ^ 1);
            CP_COMMIT();
            CP_WAIT(1);
            __syncthreads();
            const u32 aab = sbA + b * (2 * Q_A_CHUNK);
            const u32 blb = sbBl + b * Q_BL_CHUNK;
            const u32 arow = (u32)(wm*16 + (lane & 15));
            const u32 aoff = (u32)((lane >> 4) << 3);
            const u32 brow = (u32)(wn*16 + (lane & 7) + ((lane & 16) >> 1));
            const u32 b8   = (u32)(lane & 8);
#pragma unroll
            for (int ks = 0; ks < 8; ks++) {
                u32 ah[4], al[4], bhf[4], blf[4];
                ldmx4(bhf, sbBh + (brow * Q_BH_STRIDE + (u32)(s*128 + ks*16) + b8) * 2);
                ldmx4(blf, blb + (brow * Q_CH_STRIDE + (u32)(ks*16) + b8) * 2);
                u32 ad = aab + (arow * Q_CH_STRIDE + (u32)(ks*16) + aoff) * 2;
                ldmx4(ah, ad);
                ldmx4(al, ad + Q_A_CHUNK);
#pragma unroll
                for (int jn = 0; jn < 2; jn++) {
                    mma16816(acc[0][jn], ah, &bhf[jn*2]);
                    mma16816(acc[1][jn], ah, &blf[jn*2]);
                    mma16816(acc[2][jn], al, &bhf[jn*2]);
                }
            }
            __syncthreads();
        }

        // ---- epilogue: tanh(pre + sum) -> out (fp32) + hidden ring (bf16 hi/lo)
#pragma unroll
        for (int jn = 0; jn < 2; jn++) {
            int n = ntc*64 + wn*16 + jn*8 + (lane & 3) * 2;
#pragma unroll
            for (int half = 0; half < 2; half++) {
                int r = mt*32 + wm*16 + (lane >> 2) + half*8;
                float v0 = acc[0][jn][half*2]   + acc[1][jn][half*2]   + acc[2][jn][half*2];
                float v1 = acc[0][jn][half*2+1] + acc[1][jn][half*2+1] + acc[2][jn][half*2+1];
                int d = r >> 6, bidx = r & 63, t = 4*g + d;
                float* prow = out + ((size_t)bidx * SSL + t) * HH + n;
                float2 p = *(float2*)prow;
                float h0 = fast_tanh(p.x + v0);
                float h1 = fast_tanh(p.y + v1);
                *(float2*)prow = make_float2(h0, h1);
                float q0 = bf16_hi_f32(h0), q1 = bf16_hi_f32(h1);
                size_t rb = (size_t)wslot * RING + (size_t)r * HH + n;
                *(u32*)(g_rh + rb) = pack_bf16x2(h0, h1);
                *(u32*)(g_rl + rb) = pack_bf16x2(h0 - q0, h1 - q1);
            }
        }

        // ---- flag-array grid barrier (parallel arrivals + parallel polling)
        if (g + 1 < 128) {
            __threadfence();
            __syncthreads();
            const u32 tgt = my_base + (u32)g + 1u;
            if (tid == 0) ((volatile u32*)g_flags)[bid] = tgt;
            if (tid < 128) {
                while (((volatile u32*)g_flags)[tid] < tgt) { }
            }
            __syncthreads();
        }
    }
}

// ============================================================================
// Phase 3: h_final[d,b,h] = outs[b, S-4+d, h]
// ============================================================================
__global__ void copy_final_kernel(float* __restrict__ out)
{
    int idx = blockIdx.x * blockDim.x + threadIdx.x;
    const int total = 4 * BB * HH;
    if (idx < total) {
        int h  = idx & (HH - 1);
        int b  = (idx >> 10) & (BB - 1);
        int dd = idx >> 16;
        out[(size_t)BB*SSL*HH + idx] =
            out[(size_t)(b*SSL + (SSL - 4 + dd)) * HH + h];
    }
}

extern "C" void kernel_launch(void* const* d_in, const int* in_sizes, int n_in,
                              void* d_out, int out_size)
{
    const float* inputs = (const float*)d_in[0];
    const float* hidden = (const float*)d_in[1];
    const float* Wih    = (const float*)d_in[2];
    const float* Whh    = (const float*)d_in[3];
    const float* bih    = (const float*)d_in[4];
    const float* bhh    = (const float*)d_in[5];
    float* out = (float*)d_out;

    cudaFuncSetAttribute(gemm1_kernel, cudaFuncAttributeMaxDynamicSharedMemorySize, P1_BYTES);
    cudaFuncSetAttribute(rnn2_kernel,  cudaFuncAttributeMaxDynamicSharedMemorySize, Q_BYTES);

    split_kernel<<<(BB*SSL*II/4 + 255)/256, 256>>>(inputs, 0, BB*SSL*II/4);
    split_kernel<<<(II*HH/4 + 255)/256, 256>>>(Wih, 1, II*HH/4);
    split_kernel<<<(HH*HH/4 + 255)/256, 256>>>(Whh, 2, HH*HH/4);
    split_kernel<<<(4*BB*HH/4 + 255)/256, 256>>>(hidden, 3, 4*BB*HH/4);

    dim3 g1(HH/128, (BB*SSL)/128);     // (8, 256) = 2048 blocks
    gemm1_kernel<<<g1, 256, P1_BYTES>>>(bih, bhh, out);

    rnn2_kernel<<<128, 256, Q_BYTES>>>(out);

    copy_final_kernel<<<(4*BB*HH + 255)/256, 256>>>(out);
}

// round 15
// speedup vs baseline: 1.1968x; 1.1968x over previous
#include <cuda_runtime.h>
#include <cuda_bf16.h>
#include <cstdint>

#define BB 64
#define SSL 512
#define II 1024
#define HH 1024
#define RING (256*1024)

typedef unsigned int u32;
typedef unsigned long long u64;

// ---------------- persistent device scratch ----------------
__device__ __align__(256) __nv_bfloat16 g_Ahi[(size_t)BB*SSL*II];
__device__ __align__(256) __nv_bfloat16 g_Alo[(size_t)BB*SSL*II];
__device__ __align__(256) __nv_bfloat16 g_Wihh[II*HH];
__device__ __align__(256) __nv_bfloat16 g_Wihl[II*HH];
__device__ __align__(256) __nv_bfloat16 g_Whhh[HH*HH];
__device__ __align__(256) __nv_bfloat16 g_Whhl[HH*HH];
__device__ __align__(256) __nv_bfloat16 g_rh[2*RING];
__device__ __align__(256) __nv_bfloat16 g_rl[2*RING];
__device__ u32 g_flags[128];

// ---------------- helpers ----------------
__device__ __forceinline__ u32 smem_u32(const void* p) {
    u32 a; asm("{ .reg .u64 t; cvta.to.shared.u64 t, %1; cvt.u32.u64 %0, t; }" : "=r"(a) : "l"(p));
    return a;
}
__device__ __forceinline__ u32 pack_bf16x2(float a, float b) {
    u32 r; asm("cvt.rn.bf16x2.f32 %0, %1, %2;" : "=r"(r) : "f"(b), "f"(a));
    return r;
}
__device__ __forceinline__ float bf16_hi_f32(float x) {
    u32 r; asm("cvt.rn.bf16x2.f32 %0, %1, %2;" : "=r"(r) : "f"(0.0f), "f"(x));
    return __uint_as_float(r << 16);
}
__device__ __forceinline__ float fast_tanh(float x) {
    float a = fabsf(x);
    float e = __expf(-2.0f * a);
    float r = __fdividef(1.0f - e, 1.0f + e);
    return copysignf(r, x);
}
#define CP16(smem_addr, gptr) \
    asm volatile("cp.async.cg.shared.global [%0], [%1], 16;" :: "r"(smem_addr), "l"(gptr))
#define CP_COMMIT() asm volatile("cp.async.commit_group;" ::: "memory")
#define CP_WAIT(n)  asm volatile("cp.async.wait_group %0;" :: "n"(n) : "memory")

__device__ __forceinline__ void ldmx4(u32* r, u32 addr) {
    asm volatile("ldmatrix.sync.aligned.m8n8.x4.shared.b16 {%0,%1,%2,%3}, [%4];"
        : "=r"(r[0]), "=r"(r[1]), "=r"(r[2]), "=r"(r[3]) : "r"(addr));
}
__device__ __forceinline__ void mma16816(float* c, const u32* a, const u32* b) {
    asm volatile("mma.sync.aligned.m16n8k16.row.col.f32.bf16.bf16.f32 "
        "{%0,%1,%2,%3}, {%4,%5,%6,%7}, {%8,%9}, {%0,%1,%2,%3};"
        : "+f"(c[0]), "+f"(c[1]), "+f"(c[2]), "+f"(c[3])
        : "r"(a[0]), "r"(a[1]), "r"(a[2]), "r"(a[3]), "r"(b[0]), "r"(b[1]));
}

// ============================================================================
// fp32 -> bf16 hi/lo split. which: 0=inputs, 1=Wih, 2=Whh, 3=h0->ring slot0
// ============================================================================
__global__ void split_kernel(const float* __restrict__ src, int which, int n4)
{
    int i = blockIdx.x * blockDim.x + threadIdx.x;
    if (i >= n4) return;
    __nv_bfloat16 *hi, *lo;
    if      (which == 0) { hi = g_Ahi;  lo = g_Alo;  }
    else if (which == 1) { hi = g_Wihh; lo = g_Wihl; }
    else if (which == 2) { hi = g_Whhh; lo = g_Whhl; }
    else                 { hi = g_rh;   lo = g_rl;   }
    float4 v = ((const float4*)src)[i];
    float h0 = bf16_hi_f32(v.x), h1 = bf16_hi_f32(v.y);
    float h2 = bf16_hi_f32(v.z), h3 = bf16_hi_f32(v.w);
    ((u32*)hi)[2*i+0] = pack_bf16x2(v.x, v.y);
    ((u32*)hi)[2*i+1] = pack_bf16x2(v.z, v.w);
    ((u32*)lo)[2*i+0] = pack_bf16x2(v.x - h0, v.y - h1);
    ((u32*)lo)[2*i+1] = pack_bf16x2(v.z - h2, v.w - h3);
}

// ============================================================================
// Phase 1: pre = inputs @ Wih^T + bih + bhh   (mma.sync bf16, 3-product split)
// 128x128 tile, KC=64, cp.async double buffer, 256 thr, warp tile 64x32.
// ============================================================================
#define P1_AST 72
#define P1_TILE (128*P1_AST*2)     // 18432 B
#define P1_BUF  (4*P1_TILE)        // Ah Al Bh Bl
#define P1_BYTES (2*P1_BUF)        // 147456 B

__global__ __launch_bounds__(256, 1)
void gemm1_kernel(const float* __restrict__ bih, const float* __restrict__ bhh,
                  float* __restrict__ out)
{
    extern __shared__ char smem[];
    const u32 sb = smem_u32(smem);
    const int tid = threadIdx.x, wid = tid >> 5, lane = tid & 31;
    const int bm = blockIdx.y * 128, bn = blockIdx.x * 128;
    const int m_base = (wid >> 2) * 64;     // 0 or 64
    const int n_base = (wid & 3) * 32;      // 0,32,64,96

    auto load_chunk = [&](int s, int buf) {
        const int k0 = s * 64;
        const u32 base = sb + buf * P1_BUF;
#pragma unroll
        for (int it = 0; it < 4; it++) {
            int v = tid + it * 256;        // 0..1023
            int r = v >> 3, c = (v & 7) * 8;
            u32 so = (u32)(r * P1_AST + c) * 2;
            size_t gA = (size_t)(bm + r) * II + k0 + c;
            size_t gW = (size_t)(bn + r) * II + k0 + c;
            CP16(base + so,               g_Ahi + gA);
            CP16(base + P1_TILE + so,     g_Alo + gA);
            CP16(base + 2*P1_TILE + so,   g_Wihh + gW);
            CP16(base + 3*P1_TILE + so,   g_Wihl + gW);
        }
    };

    float acc[4][4][4];
#pragma unroll
    for (int i = 0; i < 4; i++)
#pragma unroll
        for (int j = 0; j < 4; j++)
#pragma unroll
            for (int q = 0; q < 4; q++) acc[i][j][q] = 0.0f;

    load_chunk(0, 0); CP_COMMIT();
    for (int s = 0; s < 16; s++) {
        const int b = s & 1;
        if (s + 1 < 16) load_chunk(s + 1, b ^ 1);
        CP_COMMIT();
        CP_WAIT(1);
        __syncthreads();
        const u32 abase = sb + b * P1_BUF;
        const u32 bbase = abase + 2 * P1_TILE;
#pragma unroll
        for (int ks = 0; ks < 4; ks++) {
            const int k16 = ks * 16;
            const u32 acol = (u32)(k16 + ((lane >> 4) << 3));
            const u32 arow = (u32)(m_base + (lane & 15));
            const u32 brow = (u32)(n_base + (lane & 7) + ((lane & 16) >> 1));
            const u32 bcol = (u32)(k16 + (lane & 8));
            u32 af[4][4], bh[8], bl[8];
#pragma unroll
            for (int j = 0; j < 2; j++) {
                u32 bd = bbase + ((brow + j*16) * P1_AST + bcol) * 2;
                ldmx4(&bh[j*4], bd);
                ldmx4(&bl[j*4], bd + P1_TILE);
            }
#pragma unroll
            for (int im = 0; im < 4; im++)
                ldmx4(af[im], abase + ((arow + im*16) * P1_AST + acol) * 2);   // Ah
#pragma unroll
            for (int im = 0; im < 4; im++)
#pragma unroll
                for (int jn = 0; jn < 4; jn++) {
                    mma16816(acc[im][jn], af[im], &bh[jn*2]);   // Ah*Bh
                    mma16816(acc[im][jn], af[im], &bl[jn*2]);   // Ah*Bl
                }
#pragma unroll
            for (int im = 0; im < 4; im++)
                ldmx4(af[im], abase + P1_TILE + ((arow + im*16) * P1_AST + acol) * 2);  // Al
#pragma unroll
            for (int im = 0; im < 4; im++)
#pragma unroll
                for (int jn = 0; jn < 4; jn++)
                    mma16816(acc[im][jn], af[im], &bh[jn*2]);   // Al*Bh
        }
        __syncthreads();
    }

    // epilogue: add biases, store fp32
#pragma unroll
    for (int im = 0; im < 4; im++) {
        int r0 = bm + m_base + im*16 + (lane >> 2);
#pragma unroll
        for (int jn = 0; jn < 4; jn++) {
            int n = bn + n_base + jn*8 + (lane & 3) * 2;
            float2 b1 = *(const float2*)(bih + n);
            float2 b2 = *(const float2*)(bhh + n);
            float bx = b1.x + b2.x, by = b1.y + b2.y;
            float2 v0 = make_float2(acc[im][jn][0] + bx, acc[im][jn][1] + by);
            float2 v1 = make_float2(acc[im][jn][2] + bx, acc[im][jn][3] + by);
            *(float2*)(out + (size_t)r0 * HH + n)       = v0;
            *(float2*)(out + (size_t)(r0+8) * HH + n)   = v1;
        }
    }
}

// ============================================================================
// Phase 2 (R11 structure + fixes): 128 blocks = 4 mt (64 rows) x 32 nt (32
// cols), 128 threads (4 warps, warp tile 32x16), Whh hi+lo fully persistent in
// SMEM, KC=128 double-buffered A, 3 accumulator sets.
// NEW: (a) per-mt flag barrier — only the 32 same-mt blocks share data, so the
// grid barrier shrinks 128->32 and uses distinct-address flags (parallel
// arrivals + parallel polls, epoch-based for graph replay).
// (b) pre-activation prefetch — each epilogue location is written exactly once
// by this thread in this group, so pre can be loaded at group start and the
// L2 latency hidden under the MMA phase.
// ============================================================================
#define P2_AST 136
#define P2_ATILE (64*P2_AST*2)     // 17408
#define P2_ABUF  (2*P2_ATILE)      // 34816
#define P2_BST 1032
#define P2_BTILE (32*P2_BST*2)     // 66048
#define P2_BYTES (2*P2_BTILE + 2*P2_ABUF)   // 201728

__global__ __launch_bounds__(128, 1)
void rnn2_kernel(float* __restrict__ out)
{
    extern __shared__ char smem[];
    const u32 sb  = smem_u32(smem);
    const u32 sbB = sb;                     // Bh, Bl at +P2_BTILE
    const u32 sbA = sb + 2 * P2_BTILE;
    const int tid = threadIdx.x, wid = tid >> 5, lane = tid & 31;
    const int bid = blockIdx.x;
    const int mt  = bid >> 5;               // 0..3  -> rows mt*64 (== delay d)
    const int ntc = bid & 31;               // 0..31 -> cols ntc*32
    const int wm = wid >> 1, wn = wid & 1;  // warp tile 32m x 16n

    const u32 my_base = *((volatile u32*)&g_flags[bid]);   // replay epoch

    // ---- persistent Whh slice (32 n-rows x 1024 k), hi+lo ----
#pragma unroll
    for (int it = 0; it < 32; it++) {
        int v = tid + it * 128;             // 0..4095
        int r = v >> 7, c = (v & 127) * 8;
        u32 so = (u32)(r * P2_BST + c) * 2;
        size_t gw = (size_t)(ntc*32 + r) * HH + c;
        CP16(sbB + so,            g_Whhh + gw);
        CP16(sbB + P2_BTILE + so, g_Whhl + gw);
    }
    CP_COMMIT(); CP_WAIT(0);
    __syncthreads();

    // fixed epilogue coordinates for this thread
    const int ep_n = ntc*32 + wn*16 + (lane & 3) * 2;  // + jn*8
    const int ep_r = mt*64 + wm*32 + (lane >> 2);      // + im*16 + half*8

    for (int g = 0; g < 128; g++) {
        const int rslot = g & 1, wslot = rslot ^ 1;
        const __nv_bfloat16* Ah = g_rh + (size_t)rslot * RING;
        const __nv_bfloat16* Al = g_rl + (size_t)rslot * RING;

        // ---- prefetch pre-activations for this group's epilogue (hidden
        //      under the MMA phase; these locations are untouched until our
        //      own store below) ----
        const int tcur = 4*g + mt;
        float2 pf[2][2][2];
#pragma unroll
        for (int im = 0; im < 2; im++)
#pragma unroll
            for (int half = 0; half < 2; half++) {
                int r = ep_r + im*16 + half*8;
                int bidx = r & 63;
                const float* prow = out + ((size_t)bidx * SSL + tcur) * HH;
#pragma unroll
                for (int jn = 0; jn < 2; jn++)
                    pf[im][jn][half] = __ldcg((const float2*)(prow + ep_n + jn*8));
            }

        auto load_a = [&](int s, int buf) {
            const int k0 = s * 128;
            const u32 base = sbA + buf * P2_ABUF;
#pragma unroll
            for (int it = 0; it < 8; it++) {
                int v = tid + it * 128;     // 0..1023
                int r = v >> 4, c = (v & 15) * 8;
                u32 so = (u32)(r * P2_AST + c) * 2;
                size_t ga = (size_t)(mt*64 + r) * HH + k0 + c;
                CP16(base + so,             Ah + ga);
                CP16(base + P2_ATILE + so,  Al + ga);
            }
        };

        float a0[2][2][4], a1[2][2][4], a2[2][2][4];
#pragma unroll
        for (int i = 0; i < 2; i++)
#pragma unroll
            for (int j = 0; j < 2; j++)
#pragma unroll
                for (int q = 0; q < 4; q++) {
                    a0[i][j][q] = 0.0f; a1[i][j][q] = 0.0f; a2[i][j][q] = 0.0f;
                }

        load_a(0, 0); CP_COMMIT();
        for (int s = 0; s < 8; s++) {
            const int b = s & 1;
            if (s + 1 < 8) load_a(s + 1, b ^ 1);
            CP_COMMIT();
            CP_WAIT(1);
            __syncthreads();
            const u32 abase = sbA + b * P2_ABUF;
#pragma unroll
            for (int ks = 0; ks < 8; ks++) {
                const int k16a = ks * 16;
                const int k16g = s * 128 + k16a;
                const u32 arow = (u32)(wm*32 + (lane & 15));
                const u32 acol = (u32)(k16a + ((lane >> 4) << 3));
                const u32 brow = (u32)(wn*16 + (lane & 7) + ((lane & 16) >> 1));
                const u32 bcol = (u32)(k16g + (lane & 8));
                u32 ah[2][4], al[2][4], bh[4], bl[4];
                u32 bd = sbB + (brow * P2_BST + bcol) * 2;
                ldmx4(bh, bd);
                ldmx4(bl, bd + P2_BTILE);
#pragma unroll
                for (int im = 0; im < 2; im++) {
                    u32 ad = abase + ((arow + im*16) * P2_AST + acol) * 2;
                    ldmx4(ah[im], ad);
                    ldmx4(al[im], ad + P2_ATILE);
                }
                // 12 independent accumulator chains per k-step
#pragma unroll
                for (int im = 0; im < 2; im++)
#pragma unroll
                    for (int jn = 0; jn < 2; jn++) {
                        mma16816(a0[im][jn], ah[im], &bh[jn*2]);
                        mma16816(a1[im][jn], ah[im], &bl[jn*2]);
                        mma16816(a2[im][jn], al[im], &bh[jn*2]);
                    }
            }
            __syncthreads();
        }

        // ---- epilogue: tanh(pre + sum) -> out (fp32) + hidden ring (bf16) ----
#pragma unroll
        for (int im = 0; im < 2; im++) {
#pragma unroll
            for (int jn = 0; jn < 2; jn++) {
                int n = ep_n + jn*8;
#pragma unroll
                for (int half = 0; half < 2; half++) {
                    int r = ep_r + im*16 + half*8;
                    float v0 = a0[im][jn][half*2]   + a1[im][jn][half*2]   + a2[im][jn][half*2];
                    float v1 = a0[im][jn][half*2+1] + a1[im][jn][half*2+1] + a2[im][jn][half*2+1];
                    int bidx = r & 63;
                    float* prow = out + ((size_t)bidx * SSL + tcur) * HH + n;
                    float2 p = pf[im][jn][half];
                    float h0 = fast_tanh(p.x + v0);
                    float h1 = fast_tanh(p.y + v1);
                    *(float2*)prow = make_float2(h0, h1);
                    float q0 = bf16_hi_f32(h0), q1 = bf16_hi_f32(h1);
                    size_t rb = (size_t)wslot * RING + (size_t)r * HH + n;
                    *(u32*)(g_rh + rb) = pack_bf16x2(h0, h1);
                    *(u32*)(g_rl + rb) = pack_bf16x2(h0 - q0, h1 - q1);
                }
            }
        }

        // ---- per-mt flag barrier: only the 32 blocks sharing this mt ----
        if (g + 1 < 128) {
            __threadfence();
            __syncthreads();
            const u32 tgt = my_base + (u32)g + 1u;
            if (tid == 0) ((volatile u32*)g_flags)[bid] = tgt;
            if (tid < 32) {
                while (((volatile u32*)g_flags)[(mt << 5) | tid] < tgt) { }
            }
            __syncthreads();
        }
    }
}

// ============================================================================
// Phase 3: h_final[d,b,h] = outs[b, S-4+d, h]
// ============================================================================
__global__ void copy_final_kernel(float* __restrict__ out)
{
    int idx = blockIdx.x * blockDim.x + threadIdx.x;
    const int total = 4 * BB * HH;
    if (idx < total) {
        int h  = idx & (HH - 1);
        int b  = (idx >> 10) & (BB - 1);
        int dd = idx >> 16;
        out[(size_t)BB*SSL*HH + idx] =
            out[(size_t)(b*SSL + (SSL - 4 + dd)) * HH + h];
    }
}

extern "C" void kernel_launch(void* const* d_in, const int* in_sizes, int n_in,
                              void* d_out, int out_size)
{
    const float* inputs = (const float*)d_in[0];
    const float* hidden = (const float*)d_in[1];
    const float* Wih    = (const float*)d_in[2];
    const float* Whh    = (const float*)d_in[3];
    const float* bih    = (const float*)d_in[4];
    const float* bhh    = (const float*)d_in[5];
    float* out = (float*)d_out;

    cudaFuncSetAttribute(gemm1_kernel, cudaFuncAttributeMaxDynamicSharedMemorySize, P1_BYTES);
    cudaFuncSetAttribute(rnn2_kernel,  cudaFuncAttributeMaxDynamicSharedMemorySize, P2_BYTES);

    split_kernel<<<(BB*SSL*II/4 + 255)/256, 256>>>(inputs, 0, BB*SSL*II/4);
    split_kernel<<<(II*HH/4 + 255)/256, 256>>>(Wih, 1, II*HH/4);
    split_kernel<<<(HH*HH/4 + 255)/256, 256>>>(Whh, 2, HH*HH/4);
    split_kernel<<<(4*BB*HH/4 + 255)/256, 256>>>(hidden, 3, 4*BB*HH/4);

    dim3 g1(HH/128, (BB*SSL)/128);     // (8, 256) = 2048 blocks
    gemm1_kernel<<<g1, 256, P1_BYTES>>>(bih, bhh, out);

    rnn2_kernel<<<128, 128, P2_BYTES>>>(out);

    copy_final_kernel<<<(4*BB*HH + 255)/256, 256>>>(out);
}

// round 16
// speedup vs baseline: 1.5501x; 1.2953x over previous
#include <cuda_runtime.h>
#include <cuda_bf16.h>
#include <cstdint>

#define BB 64
#define SSL 512
#define II 1024
#define HH 1024
#define RING (256*1024)

typedef unsigned int u32;
typedef unsigned long long u64;

// ---------------- persistent device scratch ----------------
__device__ __align__(256) __nv_bfloat16 g_Ahi[(size_t)BB*SSL*II];
__device__ __align__(256) __nv_bfloat16 g_Alo[(size_t)BB*SSL*II];
__device__ __align__(256) __nv_bfloat16 g_Wihh[II*HH];
__device__ __align__(256) __nv_bfloat16 g_Wihl[II*HH];
__device__ __align__(256) __nv_bfloat16 g_Whhh[HH*HH];
__device__ __align__(256) __nv_bfloat16 g_Whhl[HH*HH];
__device__ __align__(256) __nv_bfloat16 g_rh[2*RING];
__device__ __align__(256) __nv_bfloat16 g_rl[2*RING];
__device__ u32 g_bars[256];

// ---------------- helpers ----------------
__device__ __forceinline__ u32 smem_u32(const void* p) {
    u32 a; asm("{ .reg .u64 t; cvta.to.shared.u64 t, %1; cvt.u32.u64 %0, t; }" : "=r"(a) : "l"(p));
    return a;
}
__device__ __forceinline__ u32 pack_bf16x2(float a, float b) {
    u32 r; asm("cvt.rn.bf16x2.f32 %0, %1, %2;" : "=r"(r) : "f"(b), "f"(a));
    return r;
}
__device__ __forceinline__ float bf16_hi_f32(float x) {
    u32 r; asm("cvt.rn.bf16x2.f32 %0, %1, %2;" : "=r"(r) : "f"(0.0f), "f"(x));
    return __uint_as_float(r << 16);
}
__device__ __forceinline__ float fast_tanh(float x) {
    float a = fabsf(x);
    float e = __expf(-2.0f * a);
    float r = __fdividef(1.0f - e, 1.0f + e);
    return copysignf(r, x);
}
#define CP16(smem_addr, gptr) \
    asm volatile("cp.async.cg.shared.global [%0], [%1], 16;" :: "r"(smem_addr), "l"(gptr))
#define CP_COMMIT() asm volatile("cp.async.commit_group;" ::: "memory")
#define CP_WAIT(n)  asm volatile("cp.async.wait_group %0;" :: "n"(n) : "memory")

__device__ __forceinline__ void ldmx4(u32* r, u32 addr) {
    asm volatile("ldmatrix.sync.aligned.m8n8.x4.shared.b16 {%0,%1,%2,%3}, [%4];"
        : "=r"(r[0]), "=r"(r[1]), "=r"(r[2]), "=r"(r[3]) : "r"(addr));
}
__device__ __forceinline__ void mma16816(float* c, const u32* a, const u32* b) {
    asm volatile("mma.sync.aligned.m16n8k16.row.col.f32.bf16.bf16.f32 "
        "{%0,%1,%2,%3}, {%4,%5,%6,%7}, {%8,%9}, {%0,%1,%2,%3};"
        : "+f"(c[0]), "+f"(c[1]), "+f"(c[2]), "+f"(c[3])
        : "r"(a[0]), "r"(a[1]), "r"(a[2]), "r"(a[3]), "r"(b[0]), "r"(b[1]));
}

// ============================================================================
// fp32 -> bf16 hi/lo split, all four tensors in ONE launch.
// ============================================================================
__global__ void split_all_kernel(const float* __restrict__ inputs,
                                 const float* __restrict__ Wih,
                                 const float* __restrict__ Whh,
                                 const float* __restrict__ hidden)
{
    int i = blockIdx.x * blockDim.x + threadIdx.x;
    const int n0 = BB*SSL*II/4;
    const int n1 = n0 + II*HH/4;
    const int n2 = n1 + HH*HH/4;
    const int n3 = n2 + 4*BB*HH/4;
    const float* src; __nv_bfloat16 *hi, *lo; int j;
    if      (i < n0) { src = inputs; j = i;      hi = g_Ahi;  lo = g_Alo;  }
    else if (i < n1) { src = Wih;    j = i - n0; hi = g_Wihh; lo = g_Wihl; }
    else if (i < n2) { src = Whh;    j = i - n1; hi = g_Whhh; lo = g_Whhl; }
    else if (i < n3) { src = hidden; j = i - n2; hi = g_rh;   lo = g_rl;   }
    else return;
    float4 v = ((const float4*)src)[j];
    float h0 = bf16_hi_f32(v.x), h1 = bf16_hi_f32(v.y);
    float h2 = bf16_hi_f32(v.z), h3 = bf16_hi_f32(v.w);
    ((u32*)hi)[2*j+0] = pack_bf16x2(v.x, v.y);
    ((u32*)hi)[2*j+1] = pack_bf16x2(v.z, v.w);
    ((u32*)lo)[2*j+0] = pack_bf16x2(v.x - h0, v.y - h1);
    ((u32*)lo)[2*j+1] = pack_bf16x2(v.z - h2, v.w - h3);
}

// ============================================================================
// Phase 1: pre = inputs @ Wih^T + bih + bhh   (mma.sync bf16, 3-product split)
// 128x128 tile, KC=64, cp.async double buffer, 256 thr, warp tile 64x32.
// (unchanged from R11)
// ============================================================================
#define P1_AST 72
#define P1_TILE (128*P1_AST*2)     // 18432 B
#define P1_BUF  (4*P1_TILE)        // Ah Al Bh Bl
#define P1_BYTES (2*P1_BUF)        // 147456 B

__global__ __launch_bounds__(256, 1)
void gemm1_kernel(const float* __restrict__ bih, const float* __restrict__ bhh,
                  float* __restrict__ out)
{
    extern __shared__ char smem[];
    const u32 sb = smem_u32(smem);
    const int tid = threadIdx.x, wid = tid >> 5, lane = tid & 31;
    const int bm = blockIdx.y * 128, bn = blockIdx.x * 128;
    const int m_base = (wid >> 2) * 64;     // 0 or 64
    const int n_base = (wid & 3) * 32;      // 0,32,64,96

    auto load_chunk = [&](int s, int buf) {
        const int k0 = s * 64;
        const u32 base = sb + buf * P1_BUF;
#pragma unroll
        for (int it = 0; it < 4; it++) {
            int v = tid + it * 256;        // 0..1023
            int r = v >> 3, c = (v & 7) * 8;
            u32 so = (u32)(r * P1_AST + c) * 2;
            size_t gA = (size_t)(bm + r) * II + k0 + c;
            size_t gW = (size_t)(bn + r) * II + k0 + c;
            CP16(base + so,               g_Ahi + gA);
            CP16(base + P1_TILE + so,     g_Alo + gA);
            CP16(base + 2*P1_TILE + so,   g_Wihh + gW);
            CP16(base + 3*P1_TILE + so,   g_Wihl + gW);
        }
    };

    float acc[4][4][4];
#pragma unroll
    for (int i = 0; i < 4; i++)
#pragma unroll
        for (int j = 0; j < 4; j++)
#pragma unroll
            for (int q = 0; q < 4; q++) acc[i][j][q] = 0.0f;

    load_chunk(0, 0); CP_COMMIT();
    for (int s = 0; s < 16; s++) {
        const int b = s & 1;
        if (s + 1 < 16) load_chunk(s + 1, b ^ 1);
        CP_COMMIT();
        CP_WAIT(1);
        __syncthreads();
        const u32 abase = sb + b * P1_BUF;
        const u32 bbase = abase + 2 * P1_TILE;
#pragma unroll
        for (int ks = 0; ks < 4; ks++) {
            const int k16 = ks * 16;
            const u32 acol = (u32)(k16 + ((lane >> 4) << 3));
            const u32 arow = (u32)(m_base + (lane & 15));
            const u32 brow = (u32)(n_base + (lane & 7) + ((lane & 16) >> 1));
            const u32 bcol = (u32)(k16 + (lane & 8));
            u32 af[4][4], bh[8], bl[8];
#pragma unroll
            for (int j = 0; j < 2; j++) {
                u32 bd = bbase + ((brow + j*16) * P1_AST + bcol) * 2;
                ldmx4(&bh[j*4], bd);
                ldmx4(&bl[j*4], bd + P1_TILE);
            }
#pragma unroll
            for (int im = 0; im < 4; im++)
                ldmx4(af[im], abase + ((arow + im*16) * P1_AST + acol) * 2);   // Ah
#pragma unroll
            for (int im = 0; im < 4; im++)
#pragma unroll
                for (int jn = 0; jn < 4; jn++) {
                    mma16816(acc[im][jn], af[im], &bh[jn*2]);   // Ah*Bh
                    mma16816(acc[im][jn], af[im], &bl[jn*2]);   // Ah*Bl
                }
#pragma unroll
            for (int im = 0; im < 4; im++)
                ldmx4(af[im], abase + P1_TILE + ((arow + im*16) * P1_AST + acol) * 2);  // Al
#pragma unroll
            for (int im = 0; im < 4; im++)
#pragma unroll
                for (int jn = 0; jn < 4; jn++)
                    mma16816(acc[im][jn], af[im], &bh[jn*2]);   // Al*Bh
        }
        __syncthreads();
    }

    // epilogue: add biases, store fp32
#pragma unroll
    for (int im = 0; im < 4; im++) {
        int r0 = bm + m_base + im*16 + (lane >> 2);
#pragma unroll
        for (int jn = 0; jn < 4; jn++) {
            int n = bn + n_base + jn*8 + (lane & 3) * 2;
            float2 b1 = *(const float2*)(bih + n);
            float2 b2 = *(const float2*)(bhh + n);
            float bx = b1.x + b2.x, by = b1.y + b2.y;
            float2 v0 = make_float2(acc[im][jn][0] + bx, acc[im][jn][1] + by);
            float2 v1 = make_float2(acc[im][jn][2] + bx, acc[im][jn][3] + by);
            *(float2*)(out + (size_t)r0 * HH + n)       = v0;
            *(float2*)(out + (size_t)(r0+8) * HH + n)   = v1;
        }
    }
}

// ============================================================================
// Phase 2: R11 structure, ONE change: 256 threads (8 warps, 2/SMSP) with warp
// tile 16x16 (4m x 2n). Per-SMSP MMA count and ILP unchanged; the second warp
// per scheduler covers LDSM/L2/pipeline stalls that previously exposed a lone
// warp. Same block tile 64x32, Whh hi+lo fully SMEM-persistent, KC=128 double
// buffer, global atomic barrier, R11 epilogue.
// ============================================================================
#define P2_AST 136
#define P2_ATILE (64*P2_AST*2)     // 17408
#define P2_ABUF  (2*P2_ATILE)      // 34816
#define P2_BST 1032
#define P2_BTILE (32*P2_BST*2)     // 66048
#define P2_BYTES (2*P2_BTILE + 2*P2_ABUF)   // 201728

__global__ __launch_bounds__(256, 1)
void rnn2_kernel(float* __restrict__ out)
{
    extern __shared__ char smem[];
    const u32 sb  = smem_u32(smem);
    const u32 sbB = sb;                     // Bh, Bl at +P2_BTILE
    const u32 sbA = sb + 2 * P2_BTILE;
    const int tid = threadIdx.x, wid = tid >> 5, lane = tid & 31;
    const int mt  = blockIdx.x >> 5;        // 0..3  -> rows mt*64
    const int ntc = blockIdx.x & 31;        // 0..31 -> cols ntc*32
    const int wm = wid >> 1, wn = wid & 1;  // warp tile 16m x 16n (4m x 2n warps)
    const u32 NB = 128;

    // ---- persistent Whh slice (32 n-rows x 1024 k), hi+lo ----
#pragma unroll
    for (int it = 0; it < 16; it++) {
        int v = tid + it * 256;             // 0..4095
        int r = v >> 7, c = (v & 127) * 8;
        u32 so = (u32)(r * P2_BST + c) * 2;
        size_t gw = (size_t)(ntc*32 + r) * HH + c;
        CP16(sbB + so,            g_Whhh + gw);
        CP16(sbB + P2_BTILE + so, g_Whhl + gw);
    }
    CP_COMMIT(); CP_WAIT(0);
    __syncthreads();

    for (int g = 0; g < 128; g++) {
        const int rslot = g & 1, wslot = rslot ^ 1;
        const __nv_bfloat16* Ah = g_rh + (size_t)rslot * RING;
        const __nv_bfloat16* Al = g_rl + (size_t)rslot * RING;

        auto load_a = [&](int s, int buf) {
            const int k0 = s * 128;
            const u32 base = sbA + buf * P2_ABUF;
#pragma unroll
            for (int it = 0; it < 4; it++) {
                int v = tid + it * 256;     // 0..1023
                int r = v >> 4, c = (v & 15) * 8;
                u32 so = (u32)(r * P2_AST + c) * 2;
                size_t ga = (size_t)(mt*64 + r) * HH + k0 + c;
                CP16(base + so,             Ah + ga);
                CP16(base + P2_ATILE + so,  Al + ga);
            }
        };

        float a0[2][4], a1[2][4], a2[2][4];
#pragma unroll
        for (int j = 0; j < 2; j++)
#pragma unroll
            for (int q = 0; q < 4; q++) {
                a0[j][q] = 0.0f; a1[j][q] = 0.0f; a2[j][q] = 0.0f;
            }

        load_a(0, 0); CP_COMMIT();
        for (int s = 0; s < 8; s++) {
            const int b = s & 1;
            if (s + 1 < 8) load_a(s + 1, b ^ 1);
            CP_COMMIT();
            CP_WAIT(1);
            __syncthreads();
            const u32 abase = sbA + b * P2_ABUF;
#pragma unroll
            for (int ks = 0; ks < 8; ks++) {
                const int k16a = ks * 16;
                const int k16g = s * 128 + k16a;
                const u32 arow = (u32)(wm*16 + (lane & 15));
                const u32 acol = (u32)(k16a + ((lane >> 4) << 3));
                const u32 brow = (u32)(wn*16 + (lane & 7) + ((lane & 16) >> 1));
                const u32 bcol = (u32)(k16g + (lane & 8));
                u32 ah[4], al[4], bh[4], bl[4];
                u32 bd = sbB + (brow * P2_BST + bcol) * 2;
                ldmx4(bh, bd);
                ldmx4(bl, bd + P2_BTILE);
                u32 ad = abase + (arow * P2_AST + acol) * 2;
                ldmx4(ah, ad);
                ldmx4(al, ad + P2_ATILE);
                // 6 independent accumulator chains per warp, 12 per SMSP
#pragma unroll
                for (int jn = 0; jn < 2; jn++) {
                    mma16816(a0[jn], ah, &bh[jn*2]);
                    mma16816(a1[jn], ah, &bl[jn*2]);
                    mma16816(a2[jn], al, &bh[jn*2]);
                }
            }
            __syncthreads();
        }

        // ---- epilogue: tanh(pre + sum) -> out (fp32) + hidden ring (bf16) ----
#pragma unroll
        for (int jn = 0; jn < 2; jn++) {
            int n = ntc*32 + wn*16 + jn*8 + (lane & 3) * 2;
#pragma unroll
            for (int half = 0; half < 2; half++) {
                int r = mt*64 + wm*16 + (lane >> 2) + half*8;
                float v0 = a0[jn][half*2]   + a1[jn][half*2]   + a2[jn][half*2];
                float v1 = a0[jn][half*2+1] + a1[jn][half*2+1] + a2[jn][half*2+1];
                int d = r >> 6, bidx = r & 63, t = 4*g + d;
                float* prow = out + ((size_t)bidx * SSL + t) * HH + n;
                float2 p = *(float2*)prow;
                float h0 = fast_tanh(p.x + v0);
                float h1 = fast_tanh(p.y + v1);
                *(float2*)prow = make_float2(h0, h1);
                float q0 = bf16_hi_f32(h0), q1 = bf16_hi_f32(h1);
                size_t rb = (size_t)wslot * RING + (size_t)r * HH + n;
                *(u32*)(g_rh + rb) = pack_bf16x2(h0, h1);
                *(u32*)(g_rl + rb) = pack_bf16x2(h0 - q0, h1 - q1);
            }
        }

        // ---- grid barrier (R11: global atomic, monotonic counters) ----
        if (g + 1 < 128) {
            __threadfence();
            __syncthreads();
            if (tid == 0) {
                u32 v = atomicAdd(&g_bars[g], 1u) + 1u;
                u32 target = ((v + NB - 1u) / NB) * NB;
                while (*(volatile u32*)&g_bars[g] < target) { }
            }
            __syncthreads();
        }
    }
}

// ============================================================================
// Phase 3: h_final[d,b,h] = outs[b, S-4+d, h]
// ============================================================================
__global__ void copy_final_kernel(float* __restrict__ out)
{
    int idx = blockIdx.x * blockDim.x + threadIdx.x;
    const int total = 4 * BB * HH;
    if (idx < total) {
        int h  = idx & (HH - 1);
        int b  = (idx >> 10) & (BB - 1);
        int dd = idx >> 16;
        out[(size_t)BB*SSL*HH + idx] =
            out[(size_t)(b*SSL + (SSL - 4 + dd)) * HH + h];
    }
}

extern "C" void kernel_launch(void* const* d_in, const int* in_sizes, int n_in,
                              void* d_out, int out_size)
{
    const float* inputs = (const float*)d_in[0];
    const float* hidden = (const float*)d_in[1];
    const float* Wih    = (const float*)d_in[2];
    const float* Whh    = (const float*)d_in[3];
    const float* bih    = (const float*)d_in[4];
    const float* bhh    = (const float*)d_in[5];
    float* out = (float*)d_out;

    cudaFuncSetAttribute(gemm1_kernel, cudaFuncAttributeMaxDynamicSharedMemorySize, P1_BYTES);
    cudaFuncSetAttribute(rnn2_kernel,  cudaFuncAttributeMaxDynamicSharedMemorySize, P2_BYTES);

    const int ntot4 = (BB*SSL*II + II*HH + HH*HH + 4*BB*HH) / 4;
    split_all_kernel<<<(ntot4 + 255)/256, 256>>>(inputs, Wih, Whh, hidden);

    dim3 g1(HH/128, (BB*SSL)/128);     // (8, 256) = 2048 blocks
    gemm1_kernel<<<g1, 256, P1_BYTES>>>(bih, bhh, out);

    rnn2_kernel<<<128, 256, P2_BYTES>>>(out);

    copy_final_kernel<<<(4*BB*HH + 255)/256, 256>>>(out);
}